// round 5
// baseline (speedup 1.0000x reference)
#include <cuda_runtime.h>
#include <cuda_fp16.h>
#include <cstddef>

#define NB    512
#define NR    1152
#define NC    10
#define NO    16
#define CO    160          // NC * NO
#define NB2   256          // b-pairs

typedef unsigned long long ull;

// ---------------- scratch ----------------------------------------------------------
__device__ __half2 g_uhat2[(size_t)NB2 * NR * CO];  // 189 MB fp16, (b even, b odd) packed
__device__ float2  g_s2[NB2 * CO];                  // s accumulator, (even,odd) packed
__device__ float   g_V[NB * CO];                    // cumulative sum of squashed v
__device__ int     g_cnt[NB2];                      // pass completion counters

// ---------------- packed f32x2 helpers ---------------------------------------------
__device__ __forceinline__ ull pk2(float x, float y) {
    ull r; asm("mov.b64 %0, {%1,%2};" : "=l"(r) : "f"(x), "f"(y)); return r;
}
__device__ __forceinline__ void fma2(ull& d, ull a, ull b) {
    asm("fma.rn.f32x2 %0, %1, %2, %0;" : "+l"(d) : "l"(a), "l"(b));
}
__device__ __forceinline__ ull add2(ull a, ull b) {
    ull d; asm("add.rn.f32x2 %0, %1, %2;" : "=l"(d) : "l"(a), "l"(b)); return d;
}
__device__ __forceinline__ float2 upk2(ull v) {
    float2 f; asm("mov.b64 {%0,%1}, %2;" : "=f"(f.x), "=f"(f.y) : "l"(v)); return f;
}
__device__ __forceinline__ void redg_v2(float2* p, float x, float y) {
    asm volatile("red.global.add.v2.f32 [%0], {%1, %2};" :: "l"(p), "f"(x), "f"(y) : "memory");
}

// squash over a 16-lane o-group; all 32 lanes of the warp must call.
__device__ __forceinline__ float squash_val(float s) {
    float sq = s * s;
    sq += __shfl_xor_sync(0xffffffffu, sq, 1);
    sq += __shfl_xor_sync(0xffffffffu, sq, 2);
    sq += __shfl_xor_sync(0xffffffffu, sq, 4);
    sq += __shfl_xor_sync(0xffffffffu, sq, 8);
    return (sqrtf(sq) / (1.0f + sq)) * s;
}

// ---------------- K1: u_hat (fp16 pair-packed) + raw s0 sum ------------------------
#define K1_NBCH 2
#define K1_BCH  (NB / K1_NBCH)   // 256 b = 128 pairs per block

__global__ __launch_bounds__(256, 2) void k1_uhat(const float* __restrict__ u,
                                                  const float* __restrict__ W) {
    __shared__ __align__(16) float2 part[2][8][CO];   // double-buffered: 20 KB

    const int w = threadIdx.x >> 5;
    const int l = threadIdx.x & 31;
    const int r = blockIdx.x * 8 + w;
    const int b0 = blockIdx.y * K1_BCH;

    // W packed (w,w) in registers, hoisted out of the b-loop (80 regs)
    ull Wp[5][8];
#pragma unroll
    for (int k = 0; k < 5; k++) {
        int idx = l + 32 * k;
        const float* Wq = W + ((size_t)r * NC + (idx >> 4)) * 128 + (idx & 15);
#pragma unroll
        for (int i = 0; i < 8; i++) {
            float wv = __ldg(Wq + i * 16);
            Wp[k][i] = pk2(wv, wv);
        }
    }

    const float4* u4 = reinterpret_cast<const float4*>(u);

    for (int bp = 0; bp < K1_BCH / 2; bp++) {
        const int b = b0 + 2 * bp;
        float4 A0 = __ldg(&u4[((size_t)b * NR + r) * 2]);
        float4 A1 = __ldg(&u4[((size_t)b * NR + r) * 2 + 1]);
        float4 C0 = __ldg(&u4[((size_t)(b + 1) * NR + r) * 2]);
        float4 C1 = __ldg(&u4[((size_t)(b + 1) * NR + r) * 2 + 1]);

        ull up[8];
        up[0] = pk2(A0.x, C0.x); up[1] = pk2(A0.y, C0.y);
        up[2] = pk2(A0.z, C0.z); up[3] = pk2(A0.w, C0.w);
        up[4] = pk2(A1.x, C1.x); up[5] = pk2(A1.y, C1.y);
        up[6] = pk2(A1.z, C1.z); up[7] = pk2(A1.w, C1.w);

        __half2* outp = g_uhat2 + ((size_t)((b0 >> 1) + bp) * NR + r) * CO;
#pragma unroll
        for (int k = 0; k < 5; k++) {
            ull acc = 0ULL;
#pragma unroll
            for (int i = 0; i < 8; i++) fma2(acc, up[i], Wp[k][i]);
            float2 f = upk2(acc);
            outp[l + 32 * k] = __floats2half2_rn(f.x, f.y);
            part[bp & 1][w][l + 32 * k] = f;
        }

        if (bp & 1) {
            __syncthreads();
            const int bpg = (b0 >> 1) + bp - 1;
            const int t = threadIdx.x;
            {
                int d = (t >= CO) ? 1 : 0;
                int s = t - d * CO;                  // d0: s 0..159, d1: s 0..95
                float sx = 0.f, sy = 0.f;
#pragma unroll
                for (int ww = 0; ww < 8; ww++) {
                    float2 v = part[d][ww][s];
                    sx += v.x; sy += v.y;
                }
                redg_v2(&g_s2[(size_t)(bpg + d) * CO + s], sx, sy);
            }
            if (t < 64) {
                int s = 96 + t;                      // d1: s 96..159
                float sx = 0.f, sy = 0.f;
#pragma unroll
                for (int ww = 0; ww < 8; ww++) {
                    float2 v = part[1][ww][s];
                    sx += v.x; sy += v.y;
                }
                redg_v2(&g_s2[(size_t)(bpg + 1) * CO + s], sx, sy);
            }
            __syncthreads();
        }
    }
}

// ---------------- squash0: V = squash(0.1 * raw_sum), reset g_s2 --------------------
__global__ void k_squash0() {
    const int b2 = blockIdx.x;
    const int t = threadIdx.x;
    float2 sv = g_s2[b2 * CO + t];
    float vx = squash_val(0.1f * sv.x);
    float vy = squash_val(0.1f * sv.y);
    g_V[(2 * b2) * CO + t]     = vx;
    g_V[(2 * b2 + 1) * CO + t] = vy;
    g_s2[b2 * CO + t] = make_float2(0.f, 0.f);
}

// ---------------- pass: routing iteration + embedded squash -------------------------
#define RPB     128
#define RCHUNKS (NR / RPB)   // 9

union Q { uint4 v; __half2 h[4]; };

__global__ __launch_bounds__(256, 2) void k_pass(float* __restrict__ outp,
                                                 int final_iter) {
    __shared__ float2 part[8][CO];
    __shared__ int lastFlag;

    const int w = threadIdx.x >> 5;
    const int l = threadIdx.x & 31;
    const int b2 = blockIdx.x;
    const int rbase = blockIdx.y * RPB;
    const int g = l >> 4;
    const int c = l & 15;
    const bool act = (c < NC);

    // V for this lane's class, both batches, packed f32x2 in 16 regs
    ull Vp[16];
    if (act) {
        const float4* va = reinterpret_cast<const float4*>(g_V + (2 * b2) * CO + c * 16);
        const float4* vb = reinterpret_cast<const float4*>(g_V + (2 * b2 + 1) * CO + c * 16);
#pragma unroll
        for (int q = 0; q < 4; q++) {
            float4 x = va[q], y = vb[q];
            Vp[q * 4 + 0] = pk2(x.x, y.x);
            Vp[q * 4 + 1] = pk2(x.y, y.y);
            Vp[q * 4 + 2] = pk2(x.z, y.z);
            Vp[q * 4 + 3] = pk2(x.w, y.w);
        }
    } else {
#pragma unroll
        for (int o = 0; o < 16; o++) Vp[o] = 0ULL;
    }

    ull acc[16];
#pragma unroll
    for (int o = 0; o < 16; o++) acc[o] = 0ULL;

    const __half2* base = g_uhat2 + (size_t)b2 * NR * CO + c * 16;
#define PASS_ADDR(j) reinterpret_cast<const uint4*>(base + (size_t)(rbase + 2 * (w * 8 + (j)) + g) * CO)

    auto loadq = [&](Q* q, int j) {
        const uint4* p4 = PASS_ADDR(j);
        q[0].v = __ldcs(p4 + 0); q[1].v = __ldcs(p4 + 1);
        q[2].v = __ldcs(p4 + 2); q[3].v = __ldcs(p4 + 3);
    };

    auto body = [&](Q* q) {
        ull d0 = 0ULL, d1 = 0ULL;
        if (act) {
#pragma unroll
            for (int qq = 0; qq < 4; qq++)
#pragma unroll
                for (int m = 0; m < 4; m++) {
                    int o = qq * 4 + m;
                    float2 fv = __half22float2(q[qq].h[m]);
                    fma2((m & 1) ? d1 : d0, pk2(fv.x, fv.y), Vp[o]);
                }
        }
        float2 d = upk2(add2(d0, d1));
        float e0 = act ? __expf(d.x) : 0.0f;
        float e1 = act ? __expf(d.y) : 0.0f;
        float s0 = e0, s1 = e1;
#pragma unroll
        for (int dl = 1; dl <= 8; dl <<= 1) {
            s0 += __shfl_xor_sync(0xffffffffu, s0, dl);
            s1 += __shfl_xor_sync(0xffffffffu, s1, dl);
        }
        ull p01 = pk2(e0 * __frcp_rn(s0), e1 * __frcp_rn(s1));
        if (act) {
#pragma unroll
            for (int qq = 0; qq < 4; qq++)
#pragma unroll
                for (int m = 0; m < 4; m++) {
                    int o = qq * 4 + m;
                    float2 fv = __half22float2(q[qq].h[m]);
                    fma2(acc[o], p01, pk2(fv.x, fv.y));
                }
        }
    };

    Q qa[4], qb[4];
    if (act) loadq(qa, 0);
#pragma unroll
    for (int j = 0; j < 8; j += 2) {
        if (act) loadq(qb, j + 1);
        body(qa);
        if (act && j + 2 < 8) loadq(qa, j + 2);
        body(qb);
    }

    // combine the two 16-lane r-groups, stage into smem
#pragma unroll
    for (int o = 0; o < 16; o++) {
        float2 a = upk2(acc[o]);
        a.x += __shfl_xor_sync(0xffffffffu, a.x, 16);
        a.y += __shfl_xor_sync(0xffffffffu, a.y, 16);
        if (g == 0 && act) part[w][c * 16 + o] = a;
    }
    __syncthreads();

    if (threadIdx.x < CO) {
        float sx = 0.f, sy = 0.f;
#pragma unroll
        for (int ww = 0; ww < 8; ww++) {
            float2 v = part[ww][threadIdx.x];
            sx += v.x; sy += v.y;
        }
        redg_v2(&g_s2[b2 * CO + threadIdx.x], sx, sy);
    }

    // completion counter: last of the 9 blocks for this b2 squashes
    __threadfence();
    __syncthreads();
    if (threadIdx.x == 0)
        lastFlag = (atomicAdd(&g_cnt[b2], 1) == RCHUNKS - 1);
    __syncthreads();

    if (lastFlag) {
        __threadfence();
        const int t = threadIdx.x;
        if (t < CO) {                       // warps 0-4 fully active
            float2 sv = g_s2[b2 * CO + t];
            float vx = squash_val(sv.x);
            float vy = squash_val(sv.y);
            if (final_iter) {
                outp[(2 * b2) * CO + t]     = vx;
                outp[(2 * b2 + 1) * CO + t] = vy;
            } else {
                g_V[(2 * b2) * CO + t]     += vx;
                g_V[(2 * b2 + 1) * CO + t] += vy;
            }
            g_s2[b2 * CO + t] = make_float2(0.f, 0.f);
        }
        if (threadIdx.x == 0) g_cnt[b2] = 0;
    }
}

// ---------------- launch -------------------------------------------------------------
extern "C" void kernel_launch(void* const* d_in, const int* in_sizes, int n_in,
                              void* d_out, int out_size) {
    const float* u = (const float*)d_in[0];   // [512,1152,8]
    const float* W = (const float*)d_in[1];   // [1,1152,10,8,16]
    float* outp = (float*)d_out;              // [512,10,16]

    k1_uhat<<<dim3(NR / 8, K1_NBCH), 256>>>(u, W);     // u_hat + raw s0
    k_squash0<<<NB2, CO>>>();                          // V = squash(0.1*s0)
    k_pass<<<dim3(NB2, RCHUNKS), 256>>>(outp, 0);      // iter 1 (+squash, V+=)
    k_pass<<<dim3(NB2, RCHUNKS), 256>>>(outp, 1);      // iter 2 (+squash, -> out)
}

// round 6
// speedup vs baseline: 1.0724x; 1.0724x over previous
#include <cuda_runtime.h>
#include <cuda_fp16.h>
#include <cstddef>

#define NB    512
#define NR    1152
#define NC    10
#define NO    16
#define CO    160          // NC * NO
#define NB2   256          // b-pairs

typedef unsigned long long ull;

// ---------------- scratch ----------------------------------------------------------
__device__ __half2 g_uhat2[(size_t)NB2 * NR * CO];  // 189 MB fp16, (b even, b odd) packed
__device__ float2  g_S0[NB2 * CO];                  // raw sum_r u_hat   (from k1)
__device__ float2  g_S1[NB2 * CO];                  // s from iter 1
__device__ float2  g_S2[NB2 * CO];                  // s from iter 2
__device__ int     g_cnt[NB2];                      // pass-2 completion counters

// ---------------- packed f32x2 helpers ---------------------------------------------
__device__ __forceinline__ ull pk2(float x, float y) {
    ull r; asm("mov.b64 %0, {%1,%2};" : "=l"(r) : "f"(x), "f"(y)); return r;
}
__device__ __forceinline__ void fma2(ull& d, ull a, ull b) {
    asm("fma.rn.f32x2 %0, %1, %2, %0;" : "+l"(d) : "l"(a), "l"(b));
}
__device__ __forceinline__ ull add2(ull a, ull b) {
    ull d; asm("add.rn.f32x2 %0, %1, %2;" : "=l"(d) : "l"(a), "l"(b)); return d;
}
__device__ __forceinline__ float2 upk2(ull v) {
    float2 f; asm("mov.b64 {%0,%1}, %2;" : "=f"(f.x), "=f"(f.y) : "l"(v)); return f;
}
__device__ __forceinline__ void redg_v2(float2* p, float x, float y) {
    asm volatile("red.global.add.v2.f32 [%0], {%1, %2};" :: "l"(p), "f"(x), "f"(y) : "memory");
}

// squash over a 16-lane o-group; all 32 lanes of the warp must call.
__device__ __forceinline__ float squash_val(float s) {
    float sq = s * s;
    sq += __shfl_xor_sync(0xffffffffu, sq, 1);
    sq += __shfl_xor_sync(0xffffffffu, sq, 2);
    sq += __shfl_xor_sync(0xffffffffu, sq, 4);
    sq += __shfl_xor_sync(0xffffffffu, sq, 8);
    return (sqrtf(sq) / (1.0f + sq)) * s;
}

// ---------------- K1: u_hat (fp16 pair-packed) + raw s0 sum into S0 ----------------
#define K1_NBCH 4
#define K1_BCH  (NB / K1_NBCH)   // 128 b = 64 pairs per block

__global__ __launch_bounds__(256, 2) void k1_uhat(const float* __restrict__ u,
                                                  const float* __restrict__ W) {
    __shared__ __align__(16) float2 part[2][8][CO];   // double-buffered

    const int w = threadIdx.x >> 5;
    const int l = threadIdx.x & 31;
    const int r = blockIdx.x * 8 + w;
    const int b0 = blockIdx.y * K1_BCH;
    const int pairbase = b0 >> 1;

    float Wf[5][8];                                   // hoisted, packed per use
#pragma unroll
    for (int k = 0; k < 5; k++) {
        int idx = l + 32 * k;
        const float* Wq = W + ((size_t)r * NC + (idx >> 4)) * 128 + (idx & 15);
#pragma unroll
        for (int i = 0; i < 8; i++) Wf[k][i] = __ldg(Wq + i * 16);
    }

    const float4* u4 = reinterpret_cast<const float4*>(u);
    float4 A0 = __ldg(&u4[((size_t)b0 * NR + r) * 2]);
    float4 A1 = __ldg(&u4[((size_t)b0 * NR + r) * 2 + 1]);
    float4 C0 = __ldg(&u4[((size_t)(b0 + 1) * NR + r) * 2]);
    float4 C1 = __ldg(&u4[((size_t)(b0 + 1) * NR + r) * 2 + 1]);

    for (int bp = 0; bp < K1_BCH / 2; bp++) {
        const int b = b0 + 2 * bp;
        const int bn = (bp + 1 < K1_BCH / 2) ? b + 2 : b0;     // clamped prefetch
        float4 nA0 = __ldg(&u4[((size_t)bn * NR + r) * 2]);
        float4 nA1 = __ldg(&u4[((size_t)bn * NR + r) * 2 + 1]);
        float4 nC0 = __ldg(&u4[((size_t)(bn + 1) * NR + r) * 2]);
        float4 nC1 = __ldg(&u4[((size_t)(bn + 1) * NR + r) * 2 + 1]);

        ull up[8];
        up[0] = pk2(A0.x, C0.x); up[1] = pk2(A0.y, C0.y);
        up[2] = pk2(A0.z, C0.z); up[3] = pk2(A0.w, C0.w);
        up[4] = pk2(A1.x, C1.x); up[5] = pk2(A1.y, C1.y);
        up[6] = pk2(A1.z, C1.z); up[7] = pk2(A1.w, C1.w);

        __half2* outp = g_uhat2 + ((size_t)(pairbase + bp) * NR + r) * CO;
#pragma unroll
        for (int k = 0; k < 5; k++) {
            ull acc = 0ULL;
#pragma unroll
            for (int i = 0; i < 8; i++) fma2(acc, up[i], pk2(Wf[k][i], Wf[k][i]));
            float2 f = upk2(acc);
            outp[l + 32 * k] = __floats2half2_rn(f.x, f.y);
            part[bp & 1][w][l + 32 * k] = f;
        }

        if (bp & 1) {
            __syncthreads();
            const int bpg = pairbase + bp - 1;
            const int t = threadIdx.x;
            {
                int d = (t >= CO) ? 1 : 0;
                int s = t - d * CO;
                float sx = 0.f, sy = 0.f;
#pragma unroll
                for (int ww = 0; ww < 8; ww++) {
                    float2 v = part[d][ww][s];
                    sx += v.x; sy += v.y;
                }
                redg_v2(&g_S0[(size_t)(bpg + d) * CO + s], sx, sy);
            }
            if (t < 64) {
                int s = 96 + t;
                float sx = 0.f, sy = 0.f;
#pragma unroll
                for (int ww = 0; ww < 8; ww++) {
                    float2 v = part[1][ww][s];
                    sx += v.x; sy += v.y;
                }
                redg_v2(&g_S0[(size_t)(bpg + 1) * CO + s], sx, sy);
            }
            __syncthreads();
        }
        A0 = nA0; A1 = nA1; C0 = nC0; C1 = nC1;
    }
}

// ---------------- pass: routing iteration; V recomputed locally from S-buffers ------
#define RPB     128
#define RCHUNKS (NR / RPB)   // 9

union Q { uint4 v; __half2 h[4]; };

// Load this lane's class-row (16 float2) from an S buffer, return scaled vectors
// and write squash result into V (accumulating).
__device__ __forceinline__ void add_squash_row(const float2* __restrict__ S,
                                               int b2, int c, float scale,
                                               float2* __restrict__ V) {
    const float4* p4 = reinterpret_cast<const float4*>(S + (size_t)b2 * CO + c * 16);
    float sx[16], sy[16];
    float ssx = 0.f, ssy = 0.f;
#pragma unroll
    for (int q = 0; q < 8; q++) {
        float4 t = __ldg(p4 + q);
        sx[2 * q]     = scale * t.x; sy[2 * q]     = scale * t.y;
        sx[2 * q + 1] = scale * t.z; sy[2 * q + 1] = scale * t.w;
    }
#pragma unroll
    for (int o = 0; o < 16; o++) { ssx = fmaf(sx[o], sx[o], ssx); ssy = fmaf(sy[o], sy[o], ssy); }
    float fx = sqrtf(ssx) / (1.0f + ssx);
    float fy = sqrtf(ssy) / (1.0f + ssy);
#pragma unroll
    for (int o = 0; o < 16; o++) { V[o].x += fx * sx[o]; V[o].y += fy * sy[o]; }
}

__global__ __launch_bounds__(256, 2) void k_pass(float* __restrict__ outp,
                                                 int final_iter) {
    __shared__ float2 part[8][CO];
    __shared__ int lastFlag;

    const int w = threadIdx.x >> 5;
    const int l = threadIdx.x & 31;
    const int b2 = blockIdx.x;
    const int rbase = blockIdx.y * RPB;
    const int g = l >> 4;
    const int c = l & 15;
    const bool act = (c < NC);

    // ---- V prologue: V = squash(0.1*S0) [+ squash(S1) on final iter] --------------
    ull Vp[16];
    {
        float2 V[16];
#pragma unroll
        for (int o = 0; o < 16; o++) V[o] = make_float2(0.f, 0.f);
        if (act) {
            add_squash_row(g_S0, b2, c, 0.1f, V);
            if (final_iter) add_squash_row(g_S1, b2, c, 1.0f, V);
        }
#pragma unroll
        for (int o = 0; o < 16; o++) Vp[o] = pk2(V[o].x, V[o].y);
    }

    ull acc[16];
#pragma unroll
    for (int o = 0; o < 16; o++) acc[o] = 0ULL;

    const __half2* base = g_uhat2 + (size_t)b2 * NR * CO + c * 16;
#define PASS_ADDR(j) reinterpret_cast<const uint4*>(base + (size_t)(rbase + 2 * (w * 8 + (j)) + g) * CO)

    auto loadq = [&](Q* q, int j) {
        const uint4* p4 = PASS_ADDR(j);
        q[0].v = __ldg(p4 + 0); q[1].v = __ldg(p4 + 1);
        q[2].v = __ldg(p4 + 2); q[3].v = __ldg(p4 + 3);
    };

    auto body = [&](Q* q) {
        ull d0 = 0ULL, d1 = 0ULL;
        if (act) {
#pragma unroll
            for (int qq = 0; qq < 4; qq++)
#pragma unroll
                for (int m = 0; m < 4; m++) {
                    int o = qq * 4 + m;
                    float2 fv = __half22float2(q[qq].h[m]);
                    fma2((m & 1) ? d1 : d0, pk2(fv.x, fv.y), Vp[o]);
                }
        }
        float2 d = upk2(add2(d0, d1));
        float e0 = act ? __expf(d.x) : 0.0f;
        float e1 = act ? __expf(d.y) : 0.0f;
        float s0 = e0, s1 = e1;
#pragma unroll
        for (int dl = 1; dl <= 8; dl <<= 1) {
            s0 += __shfl_xor_sync(0xffffffffu, s0, dl);
            s1 += __shfl_xor_sync(0xffffffffu, s1, dl);
        }
        ull p01 = pk2(e0 * __frcp_rn(s0), e1 * __frcp_rn(s1));
        if (act) {
#pragma unroll
            for (int qq = 0; qq < 4; qq++)
#pragma unroll
                for (int m = 0; m < 4; m++) {
                    int o = qq * 4 + m;
                    float2 fv = __half22float2(q[qq].h[m]);
                    fma2(acc[o], p01, pk2(fv.x, fv.y));
                }
        }
    };

    Q qa[4], qb[4];
    if (act) loadq(qa, 0);
#pragma unroll
    for (int j = 0; j < 8; j += 2) {
        if (act) loadq(qb, j + 1);
        body(qa);
        if (act && j + 2 < 8) loadq(qa, j + 2);
        body(qb);
    }

    // combine the two 16-lane r-groups, stage into smem
#pragma unroll
    for (int o = 0; o < 16; o++) {
        float2 a = upk2(acc[o]);
        a.x += __shfl_xor_sync(0xffffffffu, a.x, 16);
        a.y += __shfl_xor_sync(0xffffffffu, a.y, 16);
        if (g == 0 && act) part[w][c * 16 + o] = a;
    }
    __syncthreads();

    float2* Sdst = final_iter ? g_S2 : g_S1;
    if (threadIdx.x < CO) {
        float sx = 0.f, sy = 0.f;
#pragma unroll
        for (int ww = 0; ww < 8; ww++) {
            float2 v = part[ww][threadIdx.x];
            sx += v.x; sy += v.y;
        }
        redg_v2(&Sdst[b2 * CO + threadIdx.x], sx, sy);
    }

    if (!final_iter) return;   // pass 1 has no tail

    // ---- pass-2 tail: last of the 9 blocks for this b2 squashes & resets ----------
    __threadfence();
    __syncthreads();
    if (threadIdx.x == 0)
        lastFlag = (atomicAdd(&g_cnt[b2], 1) == RCHUNKS - 1);
    __syncthreads();

    if (lastFlag) {
        __threadfence();
        const int t = threadIdx.x;
        if (t < CO) {                       // warps 0-4 fully active
            float2 sv = g_S2[b2 * CO + t];
            float vx = squash_val(sv.x);
            float vy = squash_val(sv.y);
            outp[(2 * b2) * CO + t]     = vx;
            outp[(2 * b2 + 1) * CO + t] = vy;
            g_S0[b2 * CO + t] = make_float2(0.f, 0.f);   // replay invariants
            g_S1[b2 * CO + t] = make_float2(0.f, 0.f);
            g_S2[b2 * CO + t] = make_float2(0.f, 0.f);
        }
        if (threadIdx.x == 0) g_cnt[b2] = 0;
    }
}

// ---------------- launch -------------------------------------------------------------
extern "C" void kernel_launch(void* const* d_in, const int* in_sizes, int n_in,
                              void* d_out, int out_size) {
    const float* u = (const float*)d_in[0];   // [512,1152,8]
    const float* W = (const float*)d_in[1];   // [1,1152,10,8,16]
    float* outp = (float*)d_out;              // [512,10,16]

    k1_uhat<<<dim3(NR / 8, K1_NBCH), 256>>>(u, W);     // u_hat + raw s0 -> S0
    k_pass<<<dim3(NB2, RCHUNKS), 256>>>(outp, 0);      // iter 1 -> S1
    k_pass<<<dim3(NB2, RCHUNKS), 256>>>(outp, 1);      // iter 2 -> S2 -> out, resets
}

// round 7
// speedup vs baseline: 1.0833x; 1.0102x over previous
#include <cuda_runtime.h>
#include <cuda_fp16.h>
#include <cstddef>

#define NB    512
#define NR    1152
#define NC    10
#define NO    16
#define CO    160          // NC * NO
#define NB2   256          // b-pairs

typedef unsigned long long ull;

// ---------------- scratch ----------------------------------------------------------
__device__ __half2 g_uhat2[(size_t)NB2 * NR * CO];  // 189 MB fp16, (b even, b odd) packed
__device__ float2  g_S0[NB2 * CO];                  // raw sum_r u_hat   (from k1)
__device__ float2  g_S1[NB2 * CO];                  // s from iter 1
__device__ float2  g_S2[NB2 * CO];                  // s from iter 2
__device__ int     g_cnt[NB2];                      // pass-2 completion counters

// ---------------- packed f32x2 helpers ---------------------------------------------
__device__ __forceinline__ ull pk2(float x, float y) {
    ull r; asm("mov.b64 %0, {%1,%2};" : "=l"(r) : "f"(x), "f"(y)); return r;
}
__device__ __forceinline__ void fma2(ull& d, ull a, ull b) {
    asm("fma.rn.f32x2 %0, %1, %2, %0;" : "+l"(d) : "l"(a), "l"(b));
}
__device__ __forceinline__ ull add2(ull a, ull b) {
    ull d; asm("add.rn.f32x2 %0, %1, %2;" : "=l"(d) : "l"(a), "l"(b)); return d;
}
__device__ __forceinline__ float2 upk2(ull v) {
    float2 f; asm("mov.b64 {%0,%1}, %2;" : "=f"(f.x), "=f"(f.y) : "l"(v)); return f;
}
__device__ __forceinline__ void redg_v2(float2* p, float x, float y) {
    asm volatile("red.global.add.v2.f32 [%0], {%1, %2};" :: "l"(p), "f"(x), "f"(y) : "memory");
}

// squash over a 16-lane o-group; all 32 lanes of the warp must call.
__device__ __forceinline__ float squash_val(float s) {
    float sq = s * s;
    sq += __shfl_xor_sync(0xffffffffu, sq, 1);
    sq += __shfl_xor_sync(0xffffffffu, sq, 2);
    sq += __shfl_xor_sync(0xffffffffu, sq, 4);
    sq += __shfl_xor_sync(0xffffffffu, sq, 8);
    return (sqrtf(sq) / (1.0f + sq)) * s;
}

// ---------------- K1: u_hat (fp16 pair-packed) + raw s0 sum into S0 ----------------
#define K1_NBCH 4
#define K1_BCH  (NB / K1_NBCH)   // 128 b = 64 pairs per block

__global__ __launch_bounds__(256, 2) void k1_uhat(const float* __restrict__ u,
                                                  const float* __restrict__ W) {
    __shared__ __align__(16) float2 part[2][8][CO];   // double-buffered

    const int w = threadIdx.x >> 5;
    const int l = threadIdx.x & 31;
    const int r = blockIdx.x * 8 + w;
    const int b0 = blockIdx.y * K1_BCH;
    const int pairbase = b0 >> 1;

    float Wf[5][8];                                   // hoisted, packed per use
#pragma unroll
    for (int k = 0; k < 5; k++) {
        int idx = l + 32 * k;
        const float* Wq = W + ((size_t)r * NC + (idx >> 4)) * 128 + (idx & 15);
#pragma unroll
        for (int i = 0; i < 8; i++) Wf[k][i] = __ldg(Wq + i * 16);
    }

    const float4* u4 = reinterpret_cast<const float4*>(u);
    float4 A0 = __ldg(&u4[((size_t)b0 * NR + r) * 2]);
    float4 A1 = __ldg(&u4[((size_t)b0 * NR + r) * 2 + 1]);
    float4 C0 = __ldg(&u4[((size_t)(b0 + 1) * NR + r) * 2]);
    float4 C1 = __ldg(&u4[((size_t)(b0 + 1) * NR + r) * 2 + 1]);

    for (int bp = 0; bp < K1_BCH / 2; bp++) {
        const int b = b0 + 2 * bp;
        const int bn = (bp + 1 < K1_BCH / 2) ? b + 2 : b0;     // clamped prefetch
        float4 nA0 = __ldg(&u4[((size_t)bn * NR + r) * 2]);
        float4 nA1 = __ldg(&u4[((size_t)bn * NR + r) * 2 + 1]);
        float4 nC0 = __ldg(&u4[((size_t)(bn + 1) * NR + r) * 2]);
        float4 nC1 = __ldg(&u4[((size_t)(bn + 1) * NR + r) * 2 + 1]);

        ull up[8];
        up[0] = pk2(A0.x, C0.x); up[1] = pk2(A0.y, C0.y);
        up[2] = pk2(A0.z, C0.z); up[3] = pk2(A0.w, C0.w);
        up[4] = pk2(A1.x, C1.x); up[5] = pk2(A1.y, C1.y);
        up[6] = pk2(A1.z, C1.z); up[7] = pk2(A1.w, C1.w);

        __half2* outp = g_uhat2 + ((size_t)(pairbase + bp) * NR + r) * CO;
#pragma unroll
        for (int k = 0; k < 5; k++) {
            ull acc = 0ULL;
#pragma unroll
            for (int i = 0; i < 8; i++) fma2(acc, up[i], pk2(Wf[k][i], Wf[k][i]));
            float2 f = upk2(acc);
            outp[l + 32 * k] = __floats2half2_rn(f.x, f.y);
            part[bp & 1][w][l + 32 * k] = f;
        }

        if (bp & 1) {
            __syncthreads();
            const int bpg = pairbase + bp - 1;
            const int t = threadIdx.x;
            {
                int d = (t >= CO) ? 1 : 0;
                int s = t - d * CO;
                float sx = 0.f, sy = 0.f;
#pragma unroll
                for (int ww = 0; ww < 8; ww++) {
                    float2 v = part[d][ww][s];
                    sx += v.x; sy += v.y;
                }
                redg_v2(&g_S0[(size_t)(bpg + d) * CO + s], sx, sy);
            }
            if (t < 64) {
                int s = 96 + t;
                float sx = 0.f, sy = 0.f;
#pragma unroll
                for (int ww = 0; ww < 8; ww++) {
                    float2 v = part[1][ww][s];
                    sx += v.x; sy += v.y;
                }
                redg_v2(&g_S0[(size_t)(bpg + 1) * CO + s], sx, sy);
            }
            __syncthreads();
        }
        A0 = nA0; A1 = nA1; C0 = nC0; C1 = nC1;
    }
}

// ---------------- pass: routing iteration; V recomputed locally from S-buffers ------
#define RPB     128
#define RCHUNKS (NR / RPB)   // 9

union Q { uint4 v; __half2 h[4]; };

// Load this lane's class-row (16 float2) from an S buffer, return scaled vectors
// and write squash result into V (accumulating).
__device__ __forceinline__ void add_squash_row(const float2* __restrict__ S,
                                               int b2, int c, float scale,
                                               float2* __restrict__ V) {
    const float4* p4 = reinterpret_cast<const float4*>(S + (size_t)b2 * CO + c * 16);
    float sx[16], sy[16];
    float ssx = 0.f, ssy = 0.f;
#pragma unroll
    for (int q = 0; q < 8; q++) {
        float4 t = __ldg(p4 + q);
        sx[2 * q]     = scale * t.x; sy[2 * q]     = scale * t.y;
        sx[2 * q + 1] = scale * t.z; sy[2 * q + 1] = scale * t.w;
    }
#pragma unroll
    for (int o = 0; o < 16; o++) { ssx = fmaf(sx[o], sx[o], ssx); ssy = fmaf(sy[o], sy[o], ssy); }
    float fx = sqrtf(ssx) / (1.0f + ssx);
    float fy = sqrtf(ssy) / (1.0f + ssy);
#pragma unroll
    for (int o = 0; o < 16; o++) { V[o].x += fx * sx[o]; V[o].y += fy * sy[o]; }
}

__global__ __launch_bounds__(256, 2) void k_pass(float* __restrict__ outp,
                                                 int final_iter) {
    __shared__ float2 part[8][CO];
    __shared__ int lastFlag;

    const int w = threadIdx.x >> 5;
    const int l = threadIdx.x & 31;
    const int b2 = blockIdx.x;
    const int rbase = blockIdx.y * RPB;
    const int g = l >> 4;
    const int c = l & 15;
    const bool act = (c < NC);

    // ---- V prologue: V = squash(0.1*S0) [+ squash(S1) on final iter] --------------
    ull Vp[16];
    {
        float2 V[16];
#pragma unroll
        for (int o = 0; o < 16; o++) V[o] = make_float2(0.f, 0.f);
        if (act) {
            add_squash_row(g_S0, b2, c, 0.1f, V);
            if (final_iter) add_squash_row(g_S1, b2, c, 1.0f, V);
        }
#pragma unroll
        for (int o = 0; o < 16; o++) Vp[o] = pk2(V[o].x, V[o].y);
    }

    ull acc[16];
#pragma unroll
    for (int o = 0; o < 16; o++) acc[o] = 0ULL;

    const __half2* base = g_uhat2 + (size_t)b2 * NR * CO + c * 16;
#define PASS_ADDR(j) reinterpret_cast<const uint4*>(base + (size_t)(rbase + 2 * (w * 8 + (j)) + g) * CO)

    auto loadq = [&](Q* q, int j) {
        const uint4* p4 = PASS_ADDR(j);
        q[0].v = __ldg(p4 + 0); q[1].v = __ldg(p4 + 1);
        q[2].v = __ldg(p4 + 2); q[3].v = __ldg(p4 + 3);
    };

    auto body = [&](Q* q) {
        ull d0 = 0ULL, d1 = 0ULL;
        if (act) {
#pragma unroll
            for (int qq = 0; qq < 4; qq++)
#pragma unroll
                for (int m = 0; m < 4; m++) {
                    int o = qq * 4 + m;
                    float2 fv = __half22float2(q[qq].h[m]);
                    fma2((m & 1) ? d1 : d0, pk2(fv.x, fv.y), Vp[o]);
                }
        }
        float2 d = upk2(add2(d0, d1));
        float e0 = act ? __expf(d.x) : 0.0f;
        float e1 = act ? __expf(d.y) : 0.0f;
        float s0 = e0, s1 = e1;
#pragma unroll
        for (int dl = 1; dl <= 8; dl <<= 1) {
            s0 += __shfl_xor_sync(0xffffffffu, s0, dl);
            s1 += __shfl_xor_sync(0xffffffffu, s1, dl);
        }
        ull p01 = pk2(e0 * __frcp_rn(s0), e1 * __frcp_rn(s1));
        if (act) {
#pragma unroll
            for (int qq = 0; qq < 4; qq++)
#pragma unroll
                for (int m = 0; m < 4; m++) {
                    int o = qq * 4 + m;
                    float2 fv = __half22float2(q[qq].h[m]);
                    fma2(acc[o], p01, pk2(fv.x, fv.y));
                }
        }
    };

    Q qa[4], qb[4];
    if (act) loadq(qa, 0);
#pragma unroll
    for (int j = 0; j < 8; j += 2) {
        if (act) loadq(qb, j + 1);
        body(qa);
        if (act && j + 2 < 8) loadq(qa, j + 2);
        body(qb);
    }

    // combine the two 16-lane r-groups, stage into smem
#pragma unroll
    for (int o = 0; o < 16; o++) {
        float2 a = upk2(acc[o]);
        a.x += __shfl_xor_sync(0xffffffffu, a.x, 16);
        a.y += __shfl_xor_sync(0xffffffffu, a.y, 16);
        if (g == 0 && act) part[w][c * 16 + o] = a;
    }
    __syncthreads();

    float2* Sdst = final_iter ? g_S2 : g_S1;
    if (threadIdx.x < CO) {
        float sx = 0.f, sy = 0.f;
#pragma unroll
        for (int ww = 0; ww < 8; ww++) {
            float2 v = part[ww][threadIdx.x];
            sx += v.x; sy += v.y;
        }
        redg_v2(&Sdst[b2 * CO + threadIdx.x], sx, sy);
    }

    if (!final_iter) return;   // pass 1 has no tail

    // ---- pass-2 tail: last of the 9 blocks for this b2 squashes & resets ----------
    __threadfence();
    __syncthreads();
    if (threadIdx.x == 0)
        lastFlag = (atomicAdd(&g_cnt[b2], 1) == RCHUNKS - 1);
    __syncthreads();

    if (lastFlag) {
        __threadfence();
        const int t = threadIdx.x;
        if (t < CO) {                       // warps 0-4 fully active
            float2 sv = g_S2[b2 * CO + t];
            float vx = squash_val(sv.x);
            float vy = squash_val(sv.y);
            outp[(2 * b2) * CO + t]     = vx;
            outp[(2 * b2 + 1) * CO + t] = vy;
            g_S0[b2 * CO + t] = make_float2(0.f, 0.f);   // replay invariants
            g_S1[b2 * CO + t] = make_float2(0.f, 0.f);
            g_S2[b2 * CO + t] = make_float2(0.f, 0.f);
        }
        if (threadIdx.x == 0) g_cnt[b2] = 0;
    }
}

// ---------------- launch -------------------------------------------------------------
extern "C" void kernel_launch(void* const* d_in, const int* in_sizes, int n_in,
                              void* d_out, int out_size) {
    const float* u = (const float*)d_in[0];   // [512,1152,8]
    const float* W = (const float*)d_in[1];   // [1,1152,10,8,16]
    float* outp = (float*)d_out;              // [512,10,16]

    k1_uhat<<<dim3(NR / 8, K1_NBCH), 256>>>(u, W);     // u_hat + raw s0 -> S0
    k_pass<<<dim3(NB2, RCHUNKS), 256>>>(outp, 0);      // iter 1 -> S1
    k_pass<<<dim3(NB2, RCHUNKS), 256>>>(outp, 1);      // iter 2 -> S2 -> out, resets
}

// round 8
// speedup vs baseline: 1.2226x; 1.1285x over previous
#include <cuda_runtime.h>
#include <cuda_fp16.h>
#include <cstddef>

#define NB    512
#define NR    1152
#define NC    10
#define NO    16
#define CO    160          // NC * NO
#define NB2   256          // b-pairs

// flat-permuted inner layout: f = (o>>2)*40 + c*4 + (o&3)

typedef unsigned long long ull;

// ---------------- scratch ----------------------------------------------------------
__device__ __half2 g_uhat2[(size_t)NB2 * NR * CO];  // 189 MB fp16, (even,odd) packed, f-order
__device__ float2  g_S0[NB2 * CO];                  // raw sum_r u_hat (f-order)
__device__ float2  g_S1[NB2 * CO];                  // s from iter 1   (f-order)
__device__ float2  g_S2[NB2 * CO];                  // s from iter 2   (f-order)
__device__ int     g_cnt[NB2];                      // pass-2 completion counters

// ---------------- packed f32x2 helpers ---------------------------------------------
__device__ __forceinline__ ull pk2(float x, float y) {
    ull r; asm("mov.b64 %0, {%1,%2};" : "=l"(r) : "f"(x), "f"(y)); return r;
}
__device__ __forceinline__ void fma2(ull& d, ull a, ull b) {
    asm("fma.rn.f32x2 %0, %1, %2, %0;" : "+l"(d) : "l"(a), "l"(b));
}
__device__ __forceinline__ ull add2(ull a, ull b) {
    ull d; asm("add.rn.f32x2 %0, %1, %2;" : "=l"(d) : "l"(a), "l"(b)); return d;
}
__device__ __forceinline__ float2 upk2(ull v) {
    float2 f; asm("mov.b64 {%0,%1}, %2;" : "=f"(f.x), "=f"(f.y) : "l"(v)); return f;
}
__device__ __forceinline__ void redg_v2(float2* p, float x, float y) {
    asm volatile("red.global.add.v2.f32 [%0], {%1, %2};" :: "l"(p), "f"(x), "f"(y) : "memory");
}

// squash over a 16-lane group; all 32 lanes of the warp must call.
__device__ __forceinline__ float squash_val(float s) {
    float sq = s * s;
    sq += __shfl_xor_sync(0xffffffffu, sq, 1);
    sq += __shfl_xor_sync(0xffffffffu, sq, 2);
    sq += __shfl_xor_sync(0xffffffffu, sq, 4);
    sq += __shfl_xor_sync(0xffffffffu, sq, 8);
    return (sqrtf(sq) / (1.0f + sq)) * s;
}

// ---------------- K1: u_hat (fp16 pair-packed, f-order) + raw s0 into S0 -----------
#define K1_NBCH 2
#define K1_BCH  (NB / K1_NBCH)    // 256 b
#define K1_NP   (K1_BCH / 2)      // 128 pairs per block

__global__ __launch_bounds__(256, 2) void k1_uhat(const float* __restrict__ u,
                                                  const float* __restrict__ W) {
    __shared__ __align__(16) float2 part[2][8][CO];

    const int w = threadIdx.x >> 5;
    const int l = threadIdx.x & 31;
    const int r = blockIdx.x * 8 + w;
    const int b0 = blockIdx.y * K1_BCH;
    const int pairbase = b0 >> 1;

    // lane slot k -> flat f = l + 32k -> (c,o) in permuted order
    float Wf[5][8];
#pragma unroll
    for (int k = 0; k < 5; k++) {
        int f = l + 32 * k;
        int c = (f % 40) >> 2;
        int o = (f / 40) * 4 + (f & 3);
        const float* Wq = W + ((size_t)r * NC + c) * 128 + o;
#pragma unroll
        for (int i = 0; i < 8; i++) Wf[k][i] = __ldg(Wq + i * 16);
    }

    const float4* u4 = reinterpret_cast<const float4*>(u);

    auto loadU = [&](float4* P, int bp) {
        const int b = b0 + 2 * bp;
        P[0] = __ldg(&u4[((size_t)b * NR + r) * 2]);
        P[1] = __ldg(&u4[((size_t)b * NR + r) * 2 + 1]);
        P[2] = __ldg(&u4[((size_t)(b + 1) * NR + r) * 2]);
        P[3] = __ldg(&u4[((size_t)(b + 1) * NR + r) * 2 + 1]);
    };

    auto computeOne = [&](const float4* P, int bp, int buf) {
        ull up[8];
        up[0] = pk2(P[0].x, P[2].x); up[1] = pk2(P[0].y, P[2].y);
        up[2] = pk2(P[0].z, P[2].z); up[3] = pk2(P[0].w, P[2].w);
        up[4] = pk2(P[1].x, P[3].x); up[5] = pk2(P[1].y, P[3].y);
        up[6] = pk2(P[1].z, P[3].z); up[7] = pk2(P[1].w, P[3].w);
        __half2* outp = g_uhat2 + ((size_t)(pairbase + bp) * NR + r) * CO;
#pragma unroll
        for (int k = 0; k < 5; k++) {
            ull acc = 0ULL;
#pragma unroll
            for (int i = 0; i < 8; i++) fma2(acc, up[i], pk2(Wf[k][i], Wf[k][i]));
            float2 f2 = upk2(acc);
            outp[l + 32 * k] = __floats2half2_rn(f2.x, f2.y);
            part[buf][w][l + 32 * k] = f2;
        }
    };

    auto reducePair = [&](int bpEven) {
        __syncthreads();
        const int gp = pairbase + bpEven;
        const int t = threadIdx.x;
        {
            int d = (t >= CO) ? 1 : 0;
            int s = t - d * CO;
            float sx = 0.f, sy = 0.f;
#pragma unroll
            for (int ww = 0; ww < 8; ww++) {
                float2 v = part[d][ww][s];
                sx += v.x; sy += v.y;
            }
            redg_v2(&g_S0[(size_t)(gp + d) * CO + s], sx, sy);
        }
        if (t < 64) {
            int s = 96 + t;
            float sx = 0.f, sy = 0.f;
#pragma unroll
            for (int ww = 0; ww < 8; ww++) {
                float2 v = part[1][ww][s];
                sx += v.x; sy += v.y;
            }
            redg_v2(&g_S0[(size_t)(gp + 1) * CO + s], sx, sy);
        }
        __syncthreads();
    };

    float4 A[4], B[4], C[4], D[4];
    loadU(A, 0); loadU(B, 1);

    for (int t = 0; t < K1_NP; t += 4) {
        loadU(C, t + 2); loadU(D, t + 3);        // always in range (t <= 124)
        computeOne(A, t, 0);
        computeOne(B, t + 1, 1);
        reducePair(t);
        if (t + 4 < K1_NP) { loadU(A, t + 4); loadU(B, t + 5); }
        computeOne(C, t + 2, 0);
        computeOne(D, t + 3, 1);
        reducePair(t + 2);
    }
}

// ---------------- pass: routing iteration; V recomputed locally from S-buffers ------
#define RPB     128
#define RCHUNKS (NR / RPB)   // 9

union Q { uint4 v; __half2 h[4]; };

// Gather class-c row from f-ordered S buffer, accumulate squash into V[o].
__device__ __forceinline__ void add_squash_row(const float2* __restrict__ S,
                                               int b2, int c, float scale,
                                               float2* __restrict__ V) {
    const float4* p4 = reinterpret_cast<const float4*>(S + (size_t)b2 * CO);
    float sx[16], sy[16];
    float ssx = 0.f, ssy = 0.f;
#pragma unroll
    for (int oc = 0; oc < 4; oc++)
#pragma unroll
        for (int p = 0; p < 2; p++) {
            float4 t = __ldg(p4 + oc * 20 + c * 2 + p);
            int o = oc * 4 + 2 * p;
            sx[o]     = scale * t.x; sy[o]     = scale * t.y;
            sx[o + 1] = scale * t.z; sy[o + 1] = scale * t.w;
        }
#pragma unroll
    for (int o = 0; o < 16; o++) { ssx = fmaf(sx[o], sx[o], ssx); ssy = fmaf(sy[o], sy[o], ssy); }
    float fx = sqrtf(ssx) / (1.0f + ssx);
    float fy = sqrtf(ssy) / (1.0f + ssy);
#pragma unroll
    for (int o = 0; o < 16; o++) { V[o].x += fx * sx[o]; V[o].y += fy * sy[o]; }
}

__global__ __launch_bounds__(256, 2) void k_pass(float* __restrict__ outp,
                                                 int final_iter) {
    __shared__ float2 part[8][CO];
    __shared__ int lastFlag;

    const int w = threadIdx.x >> 5;
    const int l = threadIdx.x & 31;
    const int b2 = blockIdx.x;
    const int rbase = blockIdx.y * RPB;
    const int g = l >> 4;
    const int c = l & 15;
    const bool act = (c < NC);

    // ---- V prologue: V = squash(0.1*S0) [+ squash(S1) on final iter] --------------
    ull Vp[16];
    {
        float2 V[16];
#pragma unroll
        for (int o = 0; o < 16; o++) V[o] = make_float2(0.f, 0.f);
        if (act) {
            add_squash_row(g_S0, b2, c, 0.1f, V);
            if (final_iter) add_squash_row(g_S1, b2, c, 1.0f, V);
        }
#pragma unroll
        for (int o = 0; o < 16; o++) Vp[o] = pk2(V[o].x, V[o].y);
    }

    ull acc[16];
#pragma unroll
    for (int o = 0; o < 16; o++) acc[o] = 0ULL;

    // lane reads the oc-stripes of its class: row + oc*40 + c*4 (half2 units)
    const __half2* base = g_uhat2 + (size_t)b2 * NR * CO + c * 4;
#define PASS_ROW(j) (base + (size_t)(rbase + 2 * (w * 8 + (j)) + g) * CO)

    auto loadq = [&](Q* q, int j) {
        const __half2* rp = PASS_ROW(j);
        q[0].v = __ldg(reinterpret_cast<const uint4*>(rp));
        q[1].v = __ldg(reinterpret_cast<const uint4*>(rp + 40));
        q[2].v = __ldg(reinterpret_cast<const uint4*>(rp + 80));
        q[3].v = __ldg(reinterpret_cast<const uint4*>(rp + 120));
    };

    auto body = [&](Q* q) {
        ull d0 = 0ULL, d1 = 0ULL;
        if (act) {
#pragma unroll
            for (int qq = 0; qq < 4; qq++)
#pragma unroll
                for (int m = 0; m < 4; m++) {
                    int o = qq * 4 + m;
                    float2 fv = __half22float2(q[qq].h[m]);
                    fma2((m & 1) ? d1 : d0, pk2(fv.x, fv.y), Vp[o]);
                }
        }
        float2 d = upk2(add2(d0, d1));
        float e0 = act ? __expf(d.x) : 0.0f;        // |logit| small: no max-shift
        float e1 = act ? __expf(d.y) : 0.0f;
        float s0 = e0, s1 = e1;
#pragma unroll
        for (int dl = 1; dl <= 8; dl <<= 1) {
            s0 += __shfl_xor_sync(0xffffffffu, s0, dl);
            s1 += __shfl_xor_sync(0xffffffffu, s1, dl);
        }
        ull p01 = pk2(e0 * __frcp_rn(s0), e1 * __frcp_rn(s1));
        if (act) {
#pragma unroll
            for (int qq = 0; qq < 4; qq++)
#pragma unroll
                for (int m = 0; m < 4; m++) {
                    int o = qq * 4 + m;
                    float2 fv = __half22float2(q[qq].h[m]);
                    fma2(acc[o], p01, pk2(fv.x, fv.y));
                }
        }
    };

    Q qa[4], qb[4];
    if (act) loadq(qa, 0);
#pragma unroll
    for (int j = 0; j < 8; j += 2) {
        if (act) loadq(qb, j + 1);
        body(qa);
        if (act && j + 2 < 8) loadq(qa, j + 2);
        body(qb);
    }

    // combine the two 16-lane r-groups, stage into smem (f-order)
#pragma unroll
    for (int o = 0; o < 16; o++) {
        float2 a = upk2(acc[o]);
        a.x += __shfl_xor_sync(0xffffffffu, a.x, 16);
        a.y += __shfl_xor_sync(0xffffffffu, a.y, 16);
        if (g == 0 && act) part[w][(o >> 2) * 40 + c * 4 + (o & 3)] = a;
    }
    __syncthreads();

    float2* Sdst = final_iter ? g_S2 : g_S1;
    if (threadIdx.x < CO) {
        float sx = 0.f, sy = 0.f;
#pragma unroll
        for (int ww = 0; ww < 8; ww++) {
            float2 v = part[ww][threadIdx.x];
            sx += v.x; sy += v.y;
        }
        redg_v2(&Sdst[b2 * CO + threadIdx.x], sx, sy);
    }

    if (!final_iter) return;   // pass 1 has no tail

    // ---- pass-2 tail: last of the 9 blocks for this b2 squashes & resets ----------
    __threadfence();
    __syncthreads();
    if (threadIdx.x == 0)
        lastFlag = (atomicAdd(&g_cnt[b2], 1) == RCHUNKS - 1);
    __syncthreads();

    if (lastFlag) {
        __threadfence();
        const int t = threadIdx.x;
        if (t < CO) {                       // 16-lane groups = classes (t natural order)
            int f = ((t & 15) >> 2) * 40 + ((t >> 4) << 2) + (t & 3);
            float2 sv = g_S2[b2 * CO + f];
            float vx = squash_val(sv.x);
            float vy = squash_val(sv.y);
            outp[(2 * b2) * CO + t]     = vx;
            outp[(2 * b2 + 1) * CO + t] = vy;
            g_S0[b2 * CO + f] = make_float2(0.f, 0.f);   // replay invariants
            g_S1[b2 * CO + f] = make_float2(0.f, 0.f);
            g_S2[b2 * CO + f] = make_float2(0.f, 0.f);
        }
        if (threadIdx.x == 0) g_cnt[b2] = 0;
    }
}

// ---------------- launch -------------------------------------------------------------
extern "C" void kernel_launch(void* const* d_in, const int* in_sizes, int n_in,
                              void* d_out, int out_size) {
    const float* u = (const float*)d_in[0];   // [512,1152,8]
    const float* W = (const float*)d_in[1];   // [1,1152,10,8,16]
    float* outp = (float*)d_out;              // [512,10,16]

    k1_uhat<<<dim3(NR / 8, K1_NBCH), 256>>>(u, W);     // u_hat + raw s0 -> S0
    k_pass<<<dim3(NB2, RCHUNKS), 256>>>(outp, 0);      // iter 1 -> S1
    k_pass<<<dim3(NB2, RCHUNKS), 256>>>(outp, 1);      // iter 2 -> S2 -> out, resets
}